// round 9
// baseline (speedup 1.0000x reference)
#include <cuda_runtime.h>

#define DM   2048   // d_model
#define DS   16     // d_state
#define NB   8      // batch
#define LQ   512    // seq
#define NC   8      // chunks
#define LC   64     // chunk length (NC*LC == LQ)

#define BDIM 128

typedef unsigned long long ull;

// ---- precomputed params + chunk end-state scratch ----
__device__ float g_dA [DM * DS];          // exp(dt*A)
__device__ float g_dAL[DM * DS];          // exp(LC*dt*A) = dA^LC
__device__ float g_cb [DM * DS];          // C * dt * B
__device__ float g_end[(NC - 1) * NB * DM * DS];  // end state of chunks 0..NC-2

// ---- packed f32x2 helpers ----
__device__ __forceinline__ ull pk(float lo, float hi) {
    ull r;
    asm("mov.b64 %0, {%1, %2};" : "=l"(r) : "f"(lo), "f"(hi));
    return r;
}
__device__ __forceinline__ void upk(ull v, float& lo, float& hi) {
    asm("mov.b64 {%0, %1}, %2;" : "=f"(lo), "=f"(hi) : "l"(v));
}
__device__ __forceinline__ ull fma2(ull a, ull b, ull c) {
    ull r;
    asm("fma.rn.f32x2 %0, %1, %2, %3;" : "=l"(r) : "l"(a), "l"(b), "l"(c));
    return r;
}
__device__ __forceinline__ ull mul2(ull a, ull b) {
    ull r;
    asm("mul.rn.f32x2 %0, %1, %2;" : "=l"(r) : "l"(a), "l"(b));
    return r;
}
__device__ __forceinline__ ull add2(ull a, ull b) {
    ull r;
    asm("add.rn.f32x2 %0, %1, %2;" : "=l"(r) : "l"(a), "l"(b));
    return r;
}
__device__ __forceinline__ void ld_row(const float* p, ull* v) {
#pragma unroll
    for (int k = 0; k < 4; k++) {
        float4 f = ((const float4*)p)[k];
        v[2 * k]     = pk(f.x, f.y);
        v[2 * k + 1] = pk(f.z, f.w);
    }
}

// ---- kernel 0: parameter precompute (one-shot, tiny) ----
__global__ void k_pre(const float* __restrict__ A_log,
                      const float* __restrict__ Bm,
                      const float* __restrict__ Cm,
                      const float* __restrict__ log_dt) {
    int i = blockIdx.x * blockDim.x + threadIdx.x;
    if (i >= DM * DS) return;
    int d = i >> 4;
    float dt = __expf(log_dt[d]);        // DT_SCALE = 1
    float A  = __expf(A_log[i]);
    float u  = dt * A;
    g_dA[i]  = __expf(u);
    g_dAL[i] = __expf((float)LC * u);
    g_cb[i]  = Cm[i] * (dt * Bm[i]);
}

// ---- phase A: end states of chunks 0..NC-2, full state per thread ----
__global__ void __launch_bounds__(BDIM, 8)
k_A(const float* __restrict__ x) {
    int idx = blockIdx.x * BDIM + threadIdx.x;   // (NC-1)*NB*DM = 114688
    int d = idx & (DM - 1);
    int b = (idx >> 11) & (NB - 1);
    int c = idx >> 14;                           // 0..NC-2

    ull dA2[8];
    ld_row(g_dA + (d << 4), dA2);

    ull p2[8];
#pragma unroll
    for (int k = 0; k < 8; k++) p2[k] = 0ull;

    const float* xp = x + (size_t)(b * LQ + c * LC) * DM + d;
#pragma unroll 8
    for (int t = 0; t < LC; t++) {
        float xt = xp[(size_t)t * DM];
        ull xx = pk(xt, xt);
#pragma unroll
        for (int k = 0; k < 8; k++) p2[k] = fma2(dA2[k], p2[k], xx);
    }

    float4* pe = (float4*)(g_end + ((size_t)idx << 4));
#pragma unroll
    for (int k = 0; k < 4; k++) {
        float a0, a1, a2, a3;
        upk(p2[2 * k], a0, a1);
        upk(p2[2 * k + 1], a2, a3);
        pe[k] = make_float4(a0, a1, a2, a3);
    }
}

// ---- phase C: inline chunk-init reconstruction + scan + output dot ----
__global__ void __launch_bounds__(BDIM, 8)
k_C(const float* __restrict__ x, float* __restrict__ y) {
    int idx = blockIdx.x * BDIM + threadIdx.x;   // NC*NB*DM = 131072
    int d = idx & (DM - 1);
    int b = (idx >> 11) & (NB - 1);
    int c = idx >> 14;                           // 0..NC-1, block-uniform

    ull dA2[8], cb2[8];
    ld_row(g_dA + (d << 4), dA2);
    ld_row(g_cb + (d << 4), cb2);

    ull p2[8];
#pragma unroll
    for (int k = 0; k < 8; k++) p2[k] = 0ull;

    // init = scan of prior chunk end-states with dA^LC (c uniform per warp)
    if (c > 0) {
        ull dAL2[8];
        ld_row(g_dAL + (d << 4), dAL2);
        int bd16 = ((b << 11) | d) << 4;
        for (int cc = 0; cc < c; cc++) {
            const float4* pe = (const float4*)(g_end + (size_t)(cc << 18) + bd16);
#pragma unroll
            for (int k = 0; k < 4; k++) {
                float4 v = pe[k];
                p2[2 * k]     = fma2(dAL2[2 * k],     p2[2 * k],     pk(v.x, v.y));
                p2[2 * k + 1] = fma2(dAL2[2 * k + 1], p2[2 * k + 1], pk(v.z, v.w));
            }
        }
    }

    size_t off = (size_t)(b * LQ + c * LC) * DM + d;
    const float* xp = x + off;
    float*       yp = y + off;

#pragma unroll 8
    for (int t = 0; t < LC; t++) {
        float xt = xp[(size_t)t * DM];
        ull xx = pk(xt, xt);
#pragma unroll
        for (int k = 0; k < 8; k++) p2[k] = fma2(dA2[k], p2[k], xx);

        ull acc0 = mul2(cb2[0], p2[0]);
        ull acc1 = mul2(cb2[1], p2[1]);
#pragma unroll
        for (int k = 2; k < 8; k += 2) {
            acc0 = fma2(cb2[k],     p2[k],     acc0);
            acc1 = fma2(cb2[k + 1], p2[k + 1], acc1);
        }
        ull acc = add2(acc0, acc1);
        float s0, s1;
        upk(acc, s0, s1);
        yp[(size_t)t * DM] = s0 + s1;
    }
}

extern "C" void kernel_launch(void* const* d_in, const int* in_sizes, int n_in,
                              void* d_out, int out_size) {
    const float* x      = (const float*)d_in[0];
    const float* A_log  = (const float*)d_in[1];
    const float* B      = (const float*)d_in[2];
    const float* C      = (const float*)d_in[3];
    const float* log_dt = (const float*)d_in[4];
    float* y = (float*)d_out;

    k_pre<<<(DM * DS + 255) / 256, 256>>>(A_log, B, C, log_dt);
    k_A<<<((NC - 1) * NB * DM) / BDIM, BDIM>>>(x);
    k_C<<<(NC * NB * DM) / BDIM, BDIM>>>(x, y);
}

// round 10
// speedup vs baseline: 1.0045x; 1.0045x over previous
#include <cuda_runtime.h>

#define DM   2048   // d_model
#define DS   16     // d_state
#define NB   8      // batch
#define LQ   512    // seq
#define NC   8      // chunks
#define LC   64     // chunk length (NC*LC == LQ)

#define BDIM 128

typedef unsigned long long ull;

// ---- precomputed params + chunk end-state scratch ----
__device__ float g_dA [DM * DS];          // exp(dt*A)
__device__ float g_dAL[DM * DS];          // exp(LC*dt*A) = dA^LC
__device__ float g_cb [DM * DS];          // C * dt * B
__device__ float g_end[(NC - 1) * NB * DM * DS];  // end state of chunks 0..NC-2

// ---- packed f32x2 helpers ----
__device__ __forceinline__ ull pk(float lo, float hi) {
    ull r;
    asm("mov.b64 %0, {%1, %2};" : "=l"(r) : "f"(lo), "f"(hi));
    return r;
}
__device__ __forceinline__ void upk(ull v, float& lo, float& hi) {
    asm("mov.b64 {%0, %1}, %2;" : "=f"(lo), "=f"(hi) : "l"(v));
}
__device__ __forceinline__ ull fma2(ull a, ull b, ull c) {
    ull r;
    asm("fma.rn.f32x2 %0, %1, %2, %3;" : "=l"(r) : "l"(a), "l"(b), "l"(c));
    return r;
}
__device__ __forceinline__ ull mul2(ull a, ull b) {
    ull r;
    asm("mul.rn.f32x2 %0, %1, %2;" : "=l"(r) : "l"(a), "l"(b));
    return r;
}
__device__ __forceinline__ ull add2(ull a, ull b) {
    ull r;
    asm("add.rn.f32x2 %0, %1, %2;" : "=l"(r) : "l"(a), "l"(b));
    return r;
}
__device__ __forceinline__ void ld_row(const float* p, ull* v) {
#pragma unroll
    for (int k = 0; k < 4; k++) {
        float4 f = ((const float4*)p)[k];
        v[2 * k]     = pk(f.x, f.y);
        v[2 * k + 1] = pk(f.z, f.w);
    }
}

// ---- kernel 0: parameter precompute (one-shot, tiny) ----
__global__ void k_pre(const float* __restrict__ A_log,
                      const float* __restrict__ Bm,
                      const float* __restrict__ Cm,
                      const float* __restrict__ log_dt) {
    int i = blockIdx.x * blockDim.x + threadIdx.x;
    if (i >= DM * DS) return;
    int d = i >> 4;
    float dt = __expf(log_dt[d]);        // DT_SCALE = 1
    float A  = __expf(A_log[i]);
    float u  = dt * A;
    g_dA[i]  = __expf(u);
    g_dAL[i] = __expf((float)LC * u);
    g_cb[i]  = Cm[i] * (dt * Bm[i]);
}

// ---- phase A: end states of chunks 0..NC-2, full state per thread ----
__global__ void __launch_bounds__(BDIM, 7)
k_A(const float* __restrict__ x) {
    int idx = blockIdx.x * BDIM + threadIdx.x;   // (NC-1)*NB*DM = 114688
    int d = idx & (DM - 1);
    int b = (idx >> 11) & (NB - 1);
    int c = idx >> 14;                           // 0..NC-2

    ull dA2[8];
    ld_row(g_dA + (d << 4), dA2);

    ull p2[8];
#pragma unroll
    for (int k = 0; k < 8; k++) p2[k] = 0ull;

    const float* xp = x + (size_t)(b * LQ + c * LC) * DM + d;
#pragma unroll 4
    for (int t = 0; t < LC; t++) {
        float xt = xp[(size_t)t * DM];
        ull xx = pk(xt, xt);
#pragma unroll
        for (int k = 0; k < 8; k++) p2[k] = fma2(dA2[k], p2[k], xx);
    }

    float4* pe = (float4*)(g_end + ((size_t)idx << 4));
#pragma unroll
    for (int k = 0; k < 4; k++) {
        float a0, a1, a2, a3;
        upk(p2[2 * k], a0, a1);
        upk(p2[2 * k + 1], a2, a3);
        pe[k] = make_float4(a0, a1, a2, a3);
    }
}

// ---- phase C: inline chunk-init reconstruction + scan + output dot ----
__global__ void __launch_bounds__(BDIM, 7)
k_C(const float* __restrict__ x, float* __restrict__ y) {
    int idx = blockIdx.x * BDIM + threadIdx.x;   // NC*NB*DM = 131072
    int d = idx & (DM - 1);
    int b = (idx >> 11) & (NB - 1);
    int c = idx >> 14;                           // 0..NC-1, block-uniform

    ull dA2[8], cb2[8];
    ld_row(g_dA + (d << 4), dA2);
    ld_row(g_cb + (d << 4), cb2);

    ull p2[8];
#pragma unroll
    for (int k = 0; k < 8; k++) p2[k] = 0ull;

    // init = scan of prior chunk end-states with dA^LC (c uniform per warp)
    if (c > 0) {
        ull dAL2[8];
        ld_row(g_dAL + (d << 4), dAL2);
        int bd16 = ((b << 11) | d) << 4;
        for (int cc = 0; cc < c; cc++) {
            const float4* pe = (const float4*)(g_end + (size_t)(cc << 18) + bd16);
#pragma unroll
            for (int k = 0; k < 4; k++) {
                float4 v = pe[k];
                p2[2 * k]     = fma2(dAL2[2 * k],     p2[2 * k],     pk(v.x, v.y));
                p2[2 * k + 1] = fma2(dAL2[2 * k + 1], p2[2 * k + 1], pk(v.z, v.w));
            }
        }
    }

    size_t off = (size_t)(b * LQ + c * LC) * DM + d;
    const float* xp = x + off;
    float*       yp = y + off;

#pragma unroll 4
    for (int t = 0; t < LC; t++) {
        float xt = xp[(size_t)t * DM];
        ull xx = pk(xt, xt);
#pragma unroll
        for (int k = 0; k < 8; k++) p2[k] = fma2(dA2[k], p2[k], xx);

        ull acc0 = mul2(cb2[0], p2[0]);
        ull acc1 = mul2(cb2[1], p2[1]);
#pragma unroll
        for (int k = 2; k < 8; k += 2) {
            acc0 = fma2(cb2[k],     p2[k],     acc0);
            acc1 = fma2(cb2[k + 1], p2[k + 1], acc1);
        }
        ull acc = add2(acc0, acc1);
        float s0, s1;
        upk(acc, s0, s1);
        yp[(size_t)t * DM] = s0 + s1;
    }
}

extern "C" void kernel_launch(void* const* d_in, const int* in_sizes, int n_in,
                              void* d_out, int out_size) {
    const float* x      = (const float*)d_in[0];
    const float* A_log  = (const float*)d_in[1];
    const float* B      = (const float*)d_in[2];
    const float* C      = (const float*)d_in[3];
    const float* log_dt = (const float*)d_in[4];
    float* y = (float*)d_out;

    k_pre<<<(DM * DS + 255) / 256, 256>>>(A_log, B, C, log_dt);
    k_A<<<((NC - 1) * NB * DM) / BDIM, BDIM>>>(x);
    k_C<<<(NC * NB * DM) / BDIM, BDIM>>>(x, y);
}

// round 11
// speedup vs baseline: 1.2665x; 1.2608x over previous
#include <cuda_runtime.h>

#define DM   2048   // d_model
#define DS   16     // d_state
#define NB   8      // batch
#define LQ   512    // seq
#define NC   8      // chunks
#define LC   64     // chunk length (NC*LC == LQ)

#define BDIM 128
#define BLK_PER_CHUNK (NB * DM / BDIM)       // 128 blocks per (role, chunk)
#define NBLK (((NC - 1) * 2 + 1) * BLK_PER_CHUNK)   // 1920 total

typedef unsigned long long ull;

// ---- precomputed params + chunk end-state scratch + flags ----
__device__ float g_dA [DM * DS];
__device__ float g_dAL[DM * DS];
__device__ float g_cb [DM * DS];
__device__ float g_end[(NC - 1) * NB * DM * DS];
__device__ int   g_flag[NC - 1];

// ---- packed f32x2 helpers ----
__device__ __forceinline__ ull pk(float lo, float hi) {
    ull r;
    asm("mov.b64 %0, {%1, %2};" : "=l"(r) : "f"(lo), "f"(hi));
    return r;
}
__device__ __forceinline__ void upk(ull v, float& lo, float& hi) {
    asm("mov.b64 {%0, %1}, %2;" : "=f"(lo), "=f"(hi) : "l"(v));
}
__device__ __forceinline__ ull fma2(ull a, ull b, ull c) {
    ull r;
    asm("fma.rn.f32x2 %0, %1, %2, %3;" : "=l"(r) : "l"(a), "l"(b), "l"(c));
    return r;
}
__device__ __forceinline__ ull mul2(ull a, ull b) {
    ull r;
    asm("mul.rn.f32x2 %0, %1, %2;" : "=l"(r) : "l"(a), "l"(b));
    return r;
}
__device__ __forceinline__ ull add2(ull a, ull b) {
    ull r;
    asm("add.rn.f32x2 %0, %1, %2;" : "=l"(r) : "l"(a), "l"(b));
    return r;
}
__device__ __forceinline__ void ld_row(const float* p, ull* v) {
#pragma unroll
    for (int k = 0; k < 4; k++) {
        float4 f = ((const float4*)p)[k];
        v[2 * k]     = pk(f.x, f.y);
        v[2 * k + 1] = pk(f.z, f.w);
    }
}

// ---- kernel 0: parameter precompute + flag reset (prior graph node) ----
__global__ void k_pre(const float* __restrict__ A_log,
                      const float* __restrict__ Bm,
                      const float* __restrict__ Cm,
                      const float* __restrict__ log_dt) {
    int i = blockIdx.x * blockDim.x + threadIdx.x;
    if (i < NC - 1) g_flag[i] = 0;           // replay-safe reset
    if (i >= DM * DS) return;
    int d = i >> 4;
    float dt = __expf(log_dt[d]);            // DT_SCALE = 1
    float A  = __expf(A_log[i]);
    float u  = dt * A;
    g_dA[i]  = __expf(u);
    g_dAL[i] = __expf((float)LC * u);
    g_cb[i]  = Cm[i] * (dt * Bm[i]);
}

// ---- fused pipeline kernel: bids interleaved [A0|C0|A1|C1|...|A6|C6|C7] ----
__global__ void __launch_bounds__(BDIM)
k_AC(const float* __restrict__ x, float* __restrict__ y) {
    int grp = blockIdx.x >> 8;               // 0..7 (pairs of 256 bids)
    int r   = blockIdx.x & 255;
    int isA, c, i;
    if (grp < NC - 1) { isA = (r < BLK_PER_CHUNK); c = grp; i = r & (BLK_PER_CHUNK - 1); }
    else              { isA = 0;                   c = NC - 1; i = r; }

    if (isA) {
        // ===== A role: end state of chunk c (recurrence only) =====
        int idx = (c << 14) + i * BDIM + threadIdx.x;
        int d = idx & (DM - 1);
        int b = (idx >> 11) & (NB - 1);

        ull dA2[8];
        ld_row(g_dA + (d << 4), dA2);

        ull p2[8];
#pragma unroll
        for (int k = 0; k < 8; k++) p2[k] = 0ull;

        const float* xp = x + (size_t)(b * LQ + c * LC) * DM + d;
#pragma unroll 8
        for (int t = 0; t < LC; t++) {
            float xt = xp[(size_t)t * DM];
            ull xx = pk(xt, xt);
#pragma unroll
            for (int k = 0; k < 8; k++) p2[k] = fma2(dA2[k], p2[k], xx);
        }

        float4* pe = (float4*)(g_end + ((size_t)idx << 4));
#pragma unroll
        for (int k = 0; k < 4; k++) {
            float a0, a1, a2, a3;
            upk(p2[2 * k], a0, a1);
            upk(p2[2 * k + 1], a2, a3);
            pe[k] = make_float4(a0, a1, a2, a3);
        }

        __threadfence();                      // release end-state stores
        __syncthreads();
        if (threadIdx.x == 0) atomicAdd(&g_flag[c], 1);
    } else {
        // ===== C role: wait deps, reconstruct init, scan + output =====
        int idx = (c << 14) + i * BDIM + threadIdx.x;
        int d = idx & (DM - 1);
        int b = (idx >> 11) & (NB - 1);

        if (c > 0) {
            if (threadIdx.x == 0) {
                for (int cc = 0; cc < c; cc++) {
                    while (((volatile int*)g_flag)[cc] < BLK_PER_CHUNK) __nanosleep(64);
                }
                __threadfence();              // acquire
            }
            __syncthreads();
        }

        ull dA2[8], cb2[8];
        ld_row(g_dA + (d << 4), dA2);
        ld_row(g_cb + (d << 4), cb2);

        ull p2[8];
#pragma unroll
        for (int k = 0; k < 8; k++) p2[k] = 0ull;

        if (c > 0) {
            ull dAL2[8];
            ld_row(g_dAL + (d << 4), dAL2);
            int bd16 = ((b << 11) | d) << 4;
            for (int cc = 0; cc < c; cc++) {
                const float4* pe = (const float4*)(g_end + (size_t)(cc << 18) + bd16);
#pragma unroll
                for (int k = 0; k < 4; k++) {
                    float4 v = pe[k];
                    p2[2 * k]     = fma2(dAL2[2 * k],     p2[2 * k],     pk(v.x, v.y));
                    p2[2 * k + 1] = fma2(dAL2[2 * k + 1], p2[2 * k + 1], pk(v.z, v.w));
                }
            }
        }

        size_t off = (size_t)(b * LQ + c * LC) * DM + d;
        const float* xp = x + off;
        float*       yp = y + off;

#pragma unroll 8
        for (int t = 0; t < LC; t++) {
            float xt = xp[(size_t)t * DM];
            ull xx = pk(xt, xt);
#pragma unroll
            for (int k = 0; k < 8; k++) p2[k] = fma2(dA2[k], p2[k], xx);

            ull acc0 = mul2(cb2[0], p2[0]);
            ull acc1 = mul2(cb2[1], p2[1]);
#pragma unroll
            for (int k = 2; k < 8; k += 2) {
                acc0 = fma2(cb2[k],     p2[k],     acc0);
                acc1 = fma2(cb2[k + 1], p2[k + 1], acc1);
            }
            ull acc = add2(acc0, acc1);
            float s0, s1;
            upk(acc, s0, s1);
            yp[(size_t)t * DM] = s0 + s1;
        }
    }
}

extern "C" void kernel_launch(void* const* d_in, const int* in_sizes, int n_in,
                              void* d_out, int out_size) {
    const float* x      = (const float*)d_in[0];
    const float* A_log  = (const float*)d_in[1];
    const float* B      = (const float*)d_in[2];
    const float* C      = (const float*)d_in[3];
    const float* log_dt = (const float*)d_in[4];
    float* y = (float*)d_out;

    k_pre<<<(DM * DS + 255) / 256, 256>>>(A_log, B, C, log_dt);
    k_AC<<<NBLK, BDIM>>>(x, y);
}

// round 12
// speedup vs baseline: 1.5195x; 1.1998x over previous
#include <cuda_runtime.h>

#define DM   2048   // d_model
#define DS   16     // d_state
#define NB   8      // batch
#define LQ   512    // seq
#define NC   8      // chunks
#define LC   64     // chunk length (NC*LC == LQ)

#define BDIM 128

typedef unsigned long long ull;

// ---- chunk end-state scratch (params now computed inline) ----
__device__ float g_end[(NC - 1) * NB * DM * DS];  // end state of chunks 0..NC-2

// ---- packed f32x2 helpers ----
__device__ __forceinline__ ull pk(float lo, float hi) {
    ull r;
    asm("mov.b64 %0, {%1, %2};" : "=l"(r) : "f"(lo), "f"(hi));
    return r;
}
__device__ __forceinline__ void upk(ull v, float& lo, float& hi) {
    asm("mov.b64 {%0, %1}, %2;" : "=f"(lo), "=f"(hi) : "l"(v));
}
__device__ __forceinline__ ull fma2(ull a, ull b, ull c) {
    ull r;
    asm("fma.rn.f32x2 %0, %1, %2, %3;" : "=l"(r) : "l"(a), "l"(b), "l"(c));
    return r;
}
__device__ __forceinline__ ull mul2(ull a, ull b) {
    ull r;
    asm("mul.rn.f32x2 %0, %1, %2;" : "=l"(r) : "l"(a), "l"(b));
    return r;
}
__device__ __forceinline__ ull add2(ull a, ull b) {
    ull r;
    asm("add.rn.f32x2 %0, %1, %2;" : "=l"(r) : "l"(a), "l"(b));
    return r;
}

// compute dA row (exp(dt*A)) packed as 8 f32x2; also return dt
__device__ __forceinline__ float mk_dA(const float* __restrict__ A_log,
                                       const float* __restrict__ log_dt,
                                       int d, ull* dA2) {
    float dt = __expf(log_dt[d]);        // DT_SCALE = 1
    const float4* pa = (const float4*)(A_log + (d << 4));
#pragma unroll
    for (int k = 0; k < 4; k++) {
        float4 v = pa[k];
        float a0 = __expf(dt * __expf(v.x));
        float a1 = __expf(dt * __expf(v.y));
        float a2 = __expf(dt * __expf(v.z));
        float a3 = __expf(dt * __expf(v.w));
        dA2[2 * k]     = pk(a0, a1);
        dA2[2 * k + 1] = pk(a2, a3);
    }
    return dt;
}

// ---- phase A: end states of chunks 0..NC-2, full state per thread ----
__global__ void __launch_bounds__(BDIM)
k_A(const float* __restrict__ x,
    const float* __restrict__ A_log,
    const float* __restrict__ log_dt) {
    int idx = blockIdx.x * BDIM + threadIdx.x;   // (NC-1)*NB*DM = 114688
    int d = idx & (DM - 1);
    int b = (idx >> 11) & (NB - 1);
    int c = idx >> 14;                           // 0..NC-2

    ull dA2[8];
    mk_dA(A_log, log_dt, d, dA2);

    ull p2[8];
#pragma unroll
    for (int k = 0; k < 8; k++) p2[k] = 0ull;

    const float* xp = x + (size_t)(b * LQ + c * LC) * DM + d;
#pragma unroll 8
    for (int t = 0; t < LC; t++) {
        float xt = xp[(size_t)t * DM];
        ull xx = pk(xt, xt);
#pragma unroll
        for (int k = 0; k < 8; k++) p2[k] = fma2(dA2[k], p2[k], xx);
    }

    float4* pe = (float4*)(g_end + ((size_t)idx << 4));
#pragma unroll
    for (int k = 0; k < 4; k++) {
        float a0, a1, a2, a3;
        upk(p2[2 * k], a0, a1);
        upk(p2[2 * k + 1], a2, a3);
        pe[k] = make_float4(a0, a1, a2, a3);
    }
}

// ---- phase C: inline params + chunk-init reconstruction + scan + output ----
__global__ void __launch_bounds__(BDIM)
k_C(const float* __restrict__ x,
    const float* __restrict__ A_log,
    const float* __restrict__ Bm,
    const float* __restrict__ Cm,
    const float* __restrict__ log_dt,
    float* __restrict__ y) {
    int idx = blockIdx.x * BDIM + threadIdx.x;   // NC*NB*DM = 131072
    int d = idx & (DM - 1);
    int b = (idx >> 11) & (NB - 1);
    int c = idx >> 14;                           // 0..NC-1, block-uniform

    ull dA2[8];
    float dt = mk_dA(A_log, log_dt, d, dA2);

    // cb = C * dt * B
    ull cb2[8];
    {
        const float4* pb = (const float4*)(Bm + (d << 4));
        const float4* pc = (const float4*)(Cm + (d << 4));
#pragma unroll
        for (int k = 0; k < 4; k++) {
            float4 vb = pb[k];
            float4 vc = pc[k];
            cb2[2 * k]     = pk(vc.x * (dt * vb.x), vc.y * (dt * vb.y));
            cb2[2 * k + 1] = pk(vc.z * (dt * vb.z), vc.w * (dt * vb.w));
        }
    }

    ull p2[8];
#pragma unroll
    for (int k = 0; k < 8; k++) p2[k] = 0ull;

    // init = scan of prior chunk end-states with dA^LC (c uniform per block)
    if (c > 0) {
        ull dAL2[8];
        {
            const float4* pa = (const float4*)(A_log + (d << 4));
#pragma unroll
            for (int k = 0; k < 4; k++) {
                float4 v = pa[k];
                float a0 = __expf((float)LC * dt * __expf(v.x));
                float a1 = __expf((float)LC * dt * __expf(v.y));
                float a2 = __expf((float)LC * dt * __expf(v.z));
                float a3 = __expf((float)LC * dt * __expf(v.w));
                dAL2[2 * k]     = pk(a0, a1);
                dAL2[2 * k + 1] = pk(a2, a3);
            }
        }
        int bd16 = ((b << 11) | d) << 4;
        for (int cc = 0; cc < c; cc++) {
            const float4* pe = (const float4*)(g_end + (size_t)(cc << 18) + bd16);
#pragma unroll
            for (int k = 0; k < 4; k++) {
                float4 v = pe[k];
                p2[2 * k]     = fma2(dAL2[2 * k],     p2[2 * k],     pk(v.x, v.y));
                p2[2 * k + 1] = fma2(dAL2[2 * k + 1], p2[2 * k + 1], pk(v.z, v.w));
            }
        }
    }

    size_t off = (size_t)(b * LQ + c * LC) * DM + d;
    const float* xp = x + off;
    float*       yp = y + off;

#pragma unroll 8
    for (int t = 0; t < LC; t++) {
        float xt = xp[(size_t)t * DM];
        ull xx = pk(xt, xt);
#pragma unroll
        for (int k = 0; k < 8; k++) p2[k] = fma2(dA2[k], p2[k], xx);

        ull acc0 = mul2(cb2[0], p2[0]);
        ull acc1 = mul2(cb2[1], p2[1]);
#pragma unroll
        for (int k = 2; k < 8; k += 2) {
            acc0 = fma2(cb2[k],     p2[k],     acc0);
            acc1 = fma2(cb2[k + 1], p2[k + 1], acc1);
        }
        ull acc = add2(acc0, acc1);
        float s0, s1;
        upk(acc, s0, s1);
        yp[(size_t)t * DM] = s0 + s1;
    }
}

extern "C" void kernel_launch(void* const* d_in, const int* in_sizes, int n_in,
                              void* d_out, int out_size) {
    const float* x      = (const float*)d_in[0];
    const float* A_log  = (const float*)d_in[1];
    const float* B      = (const float*)d_in[2];
    const float* C      = (const float*)d_in[3];
    const float* log_dt = (const float*)d_in[4];
    float* y = (float*)d_out;

    k_A<<<((NC - 1) * NB * DM) / BDIM, BDIM>>>(x, A_log, log_dt);
    k_C<<<(NC * NB * DM) / BDIM, BDIM>>>(x, A_log, B, C, log_dt, y);
}